// round 10
// baseline (speedup 1.0000x reference)
#include <cuda_runtime.h>
#include <cuda_bf16.h>

// Problem constants
#define OUT_NUM 1024
#define LUT_NUM 64
#define LUT_K   6
#define BR      32                 // 16 batch * 2
#define FEAT    (LUT_NUM * LUT_K)  // 384

// y(b,r,out,lut) = 6-level binary-tree lerp over wq = sigmoid(2w).
//
// R6 = R2 pair-split + depth-1 prefetch (R4 design) with the combine-weight
// SIGN BUG fixed: thread half h owns leaves with bit5==h, so its weight is
//   h=0 -> (1-b5),  h=1 -> b5    i.e.  s = (1-h) + (2h-1)*b5.
// (R4/R5 had the two swapped -> rel_err 0.183.)
//
// Rationale (R2 ncu: occ 37.9, issue 43.8, DRAM 39, FMA 25 — latency-bound):
// prefetching br+1's three LDGs above br's ~35-FFMA tree stretches the
// load-to-use distance past DRAM latency at ~26 resident warps/SM.

__global__ __launch_bounds__(128)
void lut_tree_kernel(const float* __restrict__ x,
                     const float* __restrict__ w,
                     float* __restrict__ out)
{
    const int tid  = threadIdx.x;       // 0..127
    const int lut  = tid >> 1;          // 0..63
    const int half = tid & 1;           // tree bit5

    const float c0  = half ? 0.0f : 1.0f;   // constant term of weight
    const float sgn = half ? 1.0f : -1.0f;  // s = c0 + sgn*b5
    const int o    = blockIdx.x;        // 0..1023

    // ---- my 32 contiguous w floats (128B per thread, warp fully coalesced) ----
    const float4* wp = reinterpret_cast<const float4*>(
        w + (((size_t)o * LUT_NUM + lut) << 6) + (half << 5));

    float base[16], d[16];
#pragma unroll
    for (int i = 0; i < 8; ++i) {
        float4 v = wp[i];
        // sigmoid(2w) == (tanh(w)+1)/2 ; abs err ~1e-6 << 1e-3 gate
        float s0 = __fdividef(1.0f, 1.0f + __expf(-2.0f * v.x));
        float s1 = __fdividef(1.0f, 1.0f + __expf(-2.0f * v.y));
        float s2 = __fdividef(1.0f, 1.0f + __expf(-2.0f * v.z));
        float s3 = __fdividef(1.0f, 1.0f + __expf(-2.0f * v.w));
        base[2 * i]     = s0;  d[2 * i]     = s1 - s0;
        base[2 * i + 1] = s2;  d[2 * i + 1] = s3 - s2;
    }

    // ---- per-(b,r) tree evaluation with depth-1 prefetch ----
    const float*  xp = x + (size_t)o * FEAT + lut * LUT_K;   // 8B aligned
    float*        op = out + (size_t)o * LUT_NUM + lut;
    const size_t  xstride = (size_t)OUT_NUM * FEAT;          // floats between br slices
    const size_t  ostride = (size_t)OUT_NUM * LUT_NUM;

    // prefetch br = 0
    float2 p01 = *reinterpret_cast<const float2*>(xp);
    float2 p23 = *reinterpret_cast<const float2*>(xp + 2);
    float2 p45 = *reinterpret_cast<const float2*>(xp + 4);

    for (int br = 0; br < BR; ++br) {          // NOT unrolled: L0 I$-resident body
        float2 b01 = p01, b23 = p23, b45 = p45;

        // issue next iteration's loads NOW (branchless clamp; last load redundant)
        {
            int nbr = br + 1; if (nbr > BR - 1) nbr = BR - 1;
            const float* xn = xp + (size_t)nbr * xstride;
            p01 = *reinterpret_cast<const float2*>(xn);
            p23 = *reinterpret_cast<const float2*>(xn + 2);
            p45 = *reinterpret_cast<const float2*>(xn + 4);
        }

        float y[16];
        // level 0 (bit0): cached level-0 diffs -> 1 FFMA per node
#pragma unroll
        for (int i = 0; i < 16; ++i) y[i] = fmaf(b01.x, d[i], base[i]);
        // levels 1..4
#pragma unroll
        for (int i = 0; i < 8; ++i)  y[i] = fmaf(b01.y, y[2 * i + 1] - y[2 * i], y[2 * i]);
#pragma unroll
        for (int i = 0; i < 4; ++i)  y[i] = fmaf(b23.x, y[2 * i + 1] - y[2 * i], y[2 * i]);
#pragma unroll
        for (int i = 0; i < 2; ++i)  y[i] = fmaf(b23.y, y[2 * i + 1] - y[2 * i], y[2 * i]);
        float v = fmaf(b45.x, y[1] - y[0], y[0]);   // subtree value (bits 0..4 applied)

        // level 5 (bit5), SEL-free weighted combine:
        //   half=0: s = 1-b5 ; half=1: s = b5 ;  r = s*v + shfl_pair(s*v)
        float s = fmaf(sgn, b45.y, c0);
        float m = s * v;
        float r = m + __shfl_xor_sync(0xFFFFFFFFu, m, 1);

        if (half == 0)
            op[(size_t)br * ostride] = r;
    }
}

extern "C" void kernel_launch(void* const* d_in, const int* in_sizes, int n_in,
                              void* d_out, int out_size)
{
    const float* x = (const float*)d_in[0];
    const float* w = (const float*)d_in[1];
    if (n_in >= 2 && in_sizes[0] < in_sizes[1]) {   // hedge on input order
        const float* t = x; x = w; w = t;
    }
    float* out = (float*)d_out;

    lut_tree_kernel<<<OUT_NUM, 128>>>(x, w, out);
}

// round 11
// speedup vs baseline: 1.0014x; 1.0014x over previous
#include <cuda_runtime.h>
#include <cuda_bf16.h>

// Problem constants
#define OUT_NUM 1024
#define LUT_NUM 64
#define LUT_K   6
#define BR      32                 // 16 batch * 2
#define BR_SPLIT 2                 // blocks per out-column along br
#define BR_PER  (BR / BR_SPLIT)    // 16 br slices per block
#define FEAT    (LUT_NUM * LUT_K)  // 384

// y(b,r,out,lut) = 6-level binary-tree lerp over wq = sigmoid(2w).
//
// R11 = R2 pair-split (fastest so far, 18.9us) with the warp pool doubled
// ALONG BR: each out-column's 32 br slices are split across 2 blocks (16
// each). Per-thread code is byte-identical to R2 (no extra shfl/SEL overhead
// that sank R3; no prefetch restructuring that sank R6). Grid 1024->2048
// blocks = 55 warps/SM demand vs R2's 27.7 (R2 ncu: occ 37.9, issue 43.8 ->
// classic warp-starved DRAM-latency exposure). Consecutive block pairs share
// the same o, so the duplicate w read is an L2 hit, not extra DRAM traffic.
// Combine uses the sign-FIXED weighted sum validated in R10 (rel_err 7.3e-8).

__global__ __launch_bounds__(128)
void lut_tree_kernel(const float* __restrict__ x,
                     const float* __restrict__ w,
                     float* __restrict__ out)
{
    const int tid  = threadIdx.x;        // 0..127
    const int lut  = tid >> 1;           // 0..63
    const int half = tid & 1;            // tree bit5
    const int o    = blockIdx.x >> 1;    // 0..1023  (pairs share o -> w L2 hit)
    const int sp   = blockIdx.x & 1;     // br half:  [16*sp, 16*sp+16)

    const float c0  = half ? 0.0f : 1.0f;   // weight: s = c0 + sgn*b5
    const float sgn = half ? 1.0f : -1.0f;  // h=0 -> 1-b5 ; h=1 -> b5

    // ---- my 32 contiguous w floats (128B per thread, warp fully coalesced) ----
    const float4* wp = reinterpret_cast<const float4*>(
        w + (((size_t)o * LUT_NUM + lut) << 6) + (half << 5));

    float base[16], d[16];
#pragma unroll
    for (int i = 0; i < 8; ++i) {
        float4 v = wp[i];
        // sigmoid(2w) == (tanh(w)+1)/2 ; abs err ~1e-6 << 1e-3 gate
        float s0 = __fdividef(1.0f, 1.0f + __expf(-2.0f * v.x));
        float s1 = __fdividef(1.0f, 1.0f + __expf(-2.0f * v.y));
        float s2 = __fdividef(1.0f, 1.0f + __expf(-2.0f * v.z));
        float s3 = __fdividef(1.0f, 1.0f + __expf(-2.0f * v.w));
        base[2 * i]     = s0;  d[2 * i]     = s1 - s0;
        base[2 * i + 1] = s2;  d[2 * i + 1] = s3 - s2;
    }

    // ---- per-(b,r) tree evaluation over my 16 br slices ----
    const size_t xstride = (size_t)OUT_NUM * FEAT;
    const size_t ostride = (size_t)OUT_NUM * LUT_NUM;
    const int    br0     = sp * BR_PER;

    const float* xp = x + (size_t)br0 * xstride + (size_t)o * FEAT + lut * LUT_K;
    float*       op = out + (size_t)br0 * ostride + (size_t)o * LUT_NUM + lut;

    for (int br = 0; br < BR_PER; ++br) {      // NOT unrolled: L0 I$-resident body
        const float* xb = xp + (size_t)br * xstride;
        float2 b01 = *reinterpret_cast<const float2*>(xb);       // bits 0,1
        float2 b23 = *reinterpret_cast<const float2*>(xb + 2);   // bits 2,3
        float2 b45 = *reinterpret_cast<const float2*>(xb + 4);   // bits 4,5

        float y[16];
        // level 0 (bit0): cached level-0 diffs -> 1 FFMA per node
#pragma unroll
        for (int i = 0; i < 16; ++i) y[i] = fmaf(b01.x, d[i], base[i]);
        // levels 1..4
#pragma unroll
        for (int i = 0; i < 8; ++i)  y[i] = fmaf(b01.y, y[2 * i + 1] - y[2 * i], y[2 * i]);
#pragma unroll
        for (int i = 0; i < 4; ++i)  y[i] = fmaf(b23.x, y[2 * i + 1] - y[2 * i], y[2 * i]);
#pragma unroll
        for (int i = 0; i < 2; ++i)  y[i] = fmaf(b23.y, y[2 * i + 1] - y[2 * i], y[2 * i]);
        float v = fmaf(b45.x, y[1] - y[0], y[0]);   // subtree value (bits 0..4 applied)

        // level 5 (bit5), SEL-free weighted combine (sign validated in R10):
        //   half=0: s = 1-b5 ; half=1: s = b5 ;  r = s*v + shfl_pair(s*v)
        float s = fmaf(sgn, b45.y, c0);
        float m = s * v;
        float r = m + __shfl_xor_sync(0xFFFFFFFFu, m, 1);

        if (half == 0)
            op[(size_t)br * ostride] = r;
    }
}

extern "C" void kernel_launch(void* const* d_in, const int* in_sizes, int n_in,
                              void* d_out, int out_size)
{
    const float* x = (const float*)d_in[0];
    const float* w = (const float*)d_in[1];
    if (n_in >= 2 && in_sizes[0] < in_sizes[1]) {   // hedge on input order
        const float* t = x; x = w; w = t;
    }
    float* out = (float*)d_out;

    lut_tree_kernel<<<OUT_NUM * BR_SPLIT, 128>>>(x, w, out);
}

// round 12
// speedup vs baseline: 1.2133x; 1.2117x over previous
#include <cuda_runtime.h>
#include <cuda_bf16.h>

// Problem constants
#define OUT_NUM 1024
#define LUT_NUM 64
#define LUT_K   6
#define BR      32                 // 16 batch * 2
#define FEAT    (LUT_NUM * LUT_K)  // 384

// y(b,r,out,lut) = 6-level binary-tree lerp over wq = (tanh(w)+1)/2.
//
// R12 = R2's launch geometry EXACTLY (1024 blocks x 128 thr, pair-split on
// bit5, single wave fully resident — every deviation from it regressed:
// R3 quad-split, R6 prefetch restructuring, R11 br-split all lost) with two
// instruction-stream-only changes:
//  1. preamble sigmoid via tanh.approx (1 MUFU + 1 FFMA per entry, vs
//     2 MUFU + 3 ops) — the per-block startup burst was MUFU-throughput-bound.
//  2. manual x2 br unroll: 6 LDG.64 batched up front (MLP 3 -> 6), two
//     independent trees for FFMA-latency ILP, full-warp stores (half h
//     stores slice br+h; both threads hold both results post-shfl).

__global__ __launch_bounds__(128, 7)
void lut_tree_kernel(const float* __restrict__ x,
                     const float* __restrict__ w,
                     float* __restrict__ out)
{
    const int tid  = threadIdx.x;       // 0..127
    const int lut  = tid >> 1;          // 0..63
    const int half = tid & 1;           // tree bit5
    const int o    = blockIdx.x;        // 0..1023

    const float c0  = half ? 0.0f : 1.0f;   // combine weight: s = c0 + sgn*b5
    const float sgn = half ? 1.0f : -1.0f;  // h=0 -> 1-b5 ; h=1 -> b5

    // ---- my 32 contiguous w floats (128B per thread, warp fully coalesced) ----
    const float4* wp = reinterpret_cast<const float4*>(
        w + (((size_t)o * LUT_NUM + lut) << 6) + (half << 5));

    float base[16], d[16];
#pragma unroll
    for (int i = 0; i < 8; ++i) {
        float4 v = wp[i];
        // wq = (tanh(w)+1)/2 via tanh.approx: abs err ~6e-5 -> output rel_err
        // ~1e-4, >=5x under the 1e-3 gate. 1 MUFU instead of 2 per entry.
        float t0, t1, t2, t3;
        asm("tanh.approx.f32 %0, %1;" : "=f"(t0) : "f"(v.x));
        asm("tanh.approx.f32 %0, %1;" : "=f"(t1) : "f"(v.y));
        asm("tanh.approx.f32 %0, %1;" : "=f"(t2) : "f"(v.z));
        asm("tanh.approx.f32 %0, %1;" : "=f"(t3) : "f"(v.w));
        float s0 = fmaf(0.5f, t0, 0.5f);
        float s1 = fmaf(0.5f, t1, 0.5f);
        float s2 = fmaf(0.5f, t2, 0.5f);
        float s3 = fmaf(0.5f, t3, 0.5f);
        base[2 * i]     = s0;  d[2 * i]     = s1 - s0;
        base[2 * i + 1] = s2;  d[2 * i + 1] = s3 - s2;
    }

    // ---- per-(b,r) tree evaluation, 2 slices per iteration ----
    const size_t xstride = (size_t)OUT_NUM * FEAT;
    const size_t ostride = (size_t)OUT_NUM * LUT_NUM;
    const float* xp = x + (size_t)o * FEAT + lut * LUT_K;   // 8B aligned
    float*       op = out + (size_t)o * LUT_NUM + lut + half * ostride;

    for (int br = 0; br < BR; br += 2) {       // body ~2x, still L0 I$-resident
        const float* xa = xp + (size_t)br * xstride;
        const float* xb = xa + xstride;
        // batch all 6 loads up front: MLP = 6
        float2 a01 = *reinterpret_cast<const float2*>(xa);
        float2 a23 = *reinterpret_cast<const float2*>(xa + 2);
        float2 a45 = *reinterpret_cast<const float2*>(xa + 4);
        float2 b01 = *reinterpret_cast<const float2*>(xb);
        float2 b23 = *reinterpret_cast<const float2*>(xb + 2);
        float2 b45 = *reinterpret_cast<const float2*>(xb + 4);

        // ---- tree for slice br ----
        float rA;
        {
            float y[16];
#pragma unroll
            for (int i = 0; i < 16; ++i) y[i] = fmaf(a01.x, d[i], base[i]);
#pragma unroll
            for (int i = 0; i < 8; ++i)  y[i] = fmaf(a01.y, y[2*i+1] - y[2*i], y[2*i]);
#pragma unroll
            for (int i = 0; i < 4; ++i)  y[i] = fmaf(a23.x, y[2*i+1] - y[2*i], y[2*i]);
#pragma unroll
            for (int i = 0; i < 2; ++i)  y[i] = fmaf(a23.y, y[2*i+1] - y[2*i], y[2*i]);
            float v = fmaf(a45.x, y[1] - y[0], y[0]);
            float s = fmaf(sgn, a45.y, c0);            // h=0: 1-b5, h=1: b5
            float m = s * v;
            rA = m + __shfl_xor_sync(0xFFFFFFFFu, m, 1);
        }

        // ---- tree for slice br+1 ----
        float rB;
        {
            float y[16];
#pragma unroll
            for (int i = 0; i < 16; ++i) y[i] = fmaf(b01.x, d[i], base[i]);
#pragma unroll
            for (int i = 0; i < 8; ++i)  y[i] = fmaf(b01.y, y[2*i+1] - y[2*i], y[2*i]);
#pragma unroll
            for (int i = 0; i < 4; ++i)  y[i] = fmaf(b23.x, y[2*i+1] - y[2*i], y[2*i]);
#pragma unroll
            for (int i = 0; i < 2; ++i)  y[i] = fmaf(b23.y, y[2*i+1] - y[2*i], y[2*i]);
            float v = fmaf(b45.x, y[1] - y[0], y[0]);
            float s = fmaf(sgn, b45.y, c0);
            float m = s * v;
            rB = m + __shfl_xor_sync(0xFFFFFFFFu, m, 1);
        }

        // full-warp store: half h writes slice br+h (op already offset by h)
        op[(size_t)br * ostride] = half ? rB : rA;
    }
}

extern "C" void kernel_launch(void* const* d_in, const int* in_sizes, int n_in,
                              void* d_out, int out_size)
{
    const float* x = (const float*)d_in[0];
    const float* w = (const float*)d_in[1];
    if (n_in >= 2 && in_sizes[0] < in_sizes[1]) {   // hedge on input order
        const float* t = x; x = w; w = t;
    }
    float* out = (float*)d_out;

    lut_tree_kernel<<<OUT_NUM, 128>>>(x, w, out);
}